// round 1
// baseline (speedup 1.0000x reference)
#include <cuda_runtime.h>

// ---------------------------------------------------------------------------
// Persistent fused 2-layer GRU.  B=16, C=32, L=2048, H=64.
// 512 independent sequences (scalar input), grouped S=4 per CTA -> 128 CTAs.
// Weights + x-slice resident in shared memory; f32x2 packed FMA matvecs.
// ---------------------------------------------------------------------------

namespace {
constexpr int Hh  = 64;
constexpr int G   = 192;      // 3*H
constexpr int KP  = 68;       // padded weight row stride (bank-conflict-free)
constexpr int Lh  = 2048;
constexpr int Ch  = 32;
constexpr int Bh  = 16;
constexpr int Sh  = 4;        // sequences per CTA
constexpr int NT  = 384;      // threads per CTA (12 warps, 3/SMSP)
constexpr int NCTA = (Bh * Ch) / Sh;   // 128

// shared-memory layout (float offsets)
constexpr int OFF_W0   = 0;                      // w_hh0 [192][68]
constexpr int OFF_W1I  = OFF_W0  + G * KP;       // w_ih1 [192][68]
constexpr int OFF_W1H  = OFF_W1I + G * KP;       // w_hh1 [192][68]
constexpr int OFF_XS   = OFF_W1H + G * KP;       // x slice [2048][4]
constexpr int OFF_H0   = OFF_XS  + Lh * Sh;      // h0 [4][64]
constexpr int OFF_H1   = OFF_H0  + Sh * Hh;      // h1 [4][64]
constexpr int OFF_HG0  = OFF_H1  + Sh * Hh;      // hg0 partials [2][4][192]
constexpr int OFF_IG1  = OFF_HG0 + 2 * Sh * G;   // ig1 [4][192]
constexpr int OFF_HG1  = OFF_IG1 + Sh * G;       // hg1 [4][192]
constexpr int OFF_WIH0 = OFF_HG1 + Sh * G;       // 192
constexpr int OFF_B0   = OFF_WIH0 + G;           // 192
constexpr int OFF_BN0  = OFF_B0   + G;           // 64
constexpr int OFF_B1   = OFF_BN0  + Hh;          // 192
constexpr int OFF_BN1  = OFF_B1   + G;           // 64
constexpr int SMEM_FLOATS = OFF_BN1 + Hh;
constexpr int SMEM_BYTES  = SMEM_FLOATS * 4;     // ~206.6 KB
}  // namespace

typedef unsigned long long u64;

__device__ __forceinline__ u64 ffma2(u64 a, u64 b, u64 c) {
    u64 d;
    asm("fma.rn.f32x2 %0, %1, %2, %3;" : "=l"(d) : "l"(a), "l"(b), "l"(c));
    return d;
}
__device__ __forceinline__ float red2(u64 a, u64 b) {
    float al, ah, bl, bh;
    asm("mov.b64 {%0, %1}, %2;" : "=f"(al), "=f"(ah) : "l"(a));
    asm("mov.b64 {%0, %1}, %2;" : "=f"(bl), "=f"(bh) : "l"(b));
    return (al + ah) + (bl + bh);
}
__device__ __forceinline__ float sigf(float x)  { return 1.f / (1.f + __expf(-x)); }
__device__ __forceinline__ float tanhf_(float x){ return 1.f - 2.f / (__expf(2.f * x) + 1.f); }

__device__ __forceinline__ void gate0_upd(float* sm, int s, int j, int l) {
    float xv  = sm[OFF_XS + l * 4 + s];
    int   bi  = s * G + j;
    float hr  = sm[OFF_HG0 + bi]        + sm[OFF_HG0 + Sh * G + bi];
    float hz  = sm[OFF_HG0 + bi + 64]   + sm[OFF_HG0 + Sh * G + bi + 64];
    float hn  = sm[OFF_HG0 + bi + 128]  + sm[OFF_HG0 + Sh * G + bi + 128];
    float ir  = fmaf(sm[OFF_WIH0 + j],       xv, sm[OFF_B0 + j]);
    float iz  = fmaf(sm[OFF_WIH0 + j + 64],  xv, sm[OFF_B0 + j + 64]);
    float in_ = fmaf(sm[OFF_WIH0 + j + 128], xv, sm[OFF_B0 + j + 128]);
    float r = sigf(ir + hr);
    float z = sigf(iz + hz);
    float n = tanhf_(in_ + r * (hn + sm[OFF_BN0 + j]));
    float hp = sm[OFF_H0 + s * Hh + j];
    sm[OFF_H0 + s * Hh + j] = n + z * (hp - n);
}

__device__ __forceinline__ float gate1_upd(float* sm, int s, int j) {
    int   bi  = s * G + j;
    float pr  = sm[OFF_IG1 + bi]       + sm[OFF_HG1 + bi]       + sm[OFF_B1 + j];
    float pz  = sm[OFF_IG1 + bi + 64]  + sm[OFF_HG1 + bi + 64]  + sm[OFF_B1 + j + 64];
    float in_ = sm[OFF_IG1 + bi + 128] + sm[OFF_B1 + j + 128];
    float hgn = sm[OFF_HG1 + bi + 128] + sm[OFF_BN1 + j];
    float r = sigf(pr);
    float z = sigf(pz);
    float n = tanhf_(in_ + r * hgn);
    float hp = sm[OFF_H1 + s * Hh + j];
    float hnew = n + z * (hp - n);
    sm[OFF_H1 + s * Hh + j] = hnew;
    return hnew;
}

__global__ __launch_bounds__(NT, 1)
void gru2_kernel(const float* __restrict__ x,
                 const float* __restrict__ w_ih0, const float* __restrict__ w_hh0,
                 const float* __restrict__ b0,    const float* __restrict__ bn0,
                 const float* __restrict__ w_ih1, const float* __restrict__ w_hh1,
                 const float* __restrict__ b1,    const float* __restrict__ bn1,
                 float* __restrict__ out)
{
    extern __shared__ float sm[];
    const int t  = threadIdx.x;
    const int m  = blockIdx.x;
    const int b  = m >> 3;
    const int c0 = (m & 7) * 4;

    // ---- one-time loads: weights (padded), biases, x slice, h init --------
    for (int i = t; i < G * Hh; i += NT) {
        int r = i >> 6, k = i & 63;
        sm[OFF_W0  + r * KP + k] = w_hh0[i];
        sm[OFF_W1I + r * KP + k] = w_ih1[i];
        sm[OFF_W1H + r * KP + k] = w_hh1[i];
    }
    for (int i = t; i < G; i += NT) {
        sm[OFF_WIH0 + i] = w_ih0[i];
        sm[OFF_B0 + i]   = b0[i];
        sm[OFF_B1 + i]   = b1[i];
    }
    for (int i = t; i < Hh; i += NT) {
        sm[OFF_BN0 + i] = bn0[i];
        sm[OFF_BN1 + i] = bn1[i];
    }
    {
        const float* xg = x + (long)b * Lh * Ch + c0;
        for (int l = t; l < Lh; l += NT) {
            float4 v = *(const float4*)(xg + (long)l * Ch);
            *(float4*)(sm + OFF_XS + l * 4) = v;
        }
    }
    for (int i = t; i < 2 * Sh * Hh; i += NT) sm[OFF_H0 + i] = 0.f;
    __syncthreads();

    float* outc = out + (long)(b * Ch + c0) * Lh * Hh;

    const int kh  = (t >= 192) ? 1 : 0;   // warp-uniform K-half (phase A)
    const int rA  = t - kh * 192;         // row for phase A
    const int gB  = (t >= 192) ? 1 : 0;   // warp-uniform group (phase B)
    const int rB  = t - gB * 192;         // row for phase B
    const float* wrA  = sm + OFF_W0 + rA * KP + kh * 32;
    const float* hbA  = sm + OFF_H0 + kh * 32;
    const float* wrB  = sm + (gB ? OFF_W1H : OFF_W1I) + rB * KP;
    const float* srcB = sm + (gB ? OFF_H1 : OFF_H0);
    float*       dstB = sm + (gB ? OFF_HG1 : OFF_IG1);
    const int gs = t >> 6, gj = t & 63;   // gate-unit mapping (t < 256)

    for (int l = 0; l < Lh; ++l) {
        // ---- Phase A: hg0 partials  (K split in halves across thread groups)
        {
            u64 a0 = 0, a1 = 0, a2 = 0, a3 = 0, e0 = 0, e1 = 0, e2 = 0, e3 = 0;
            #pragma unroll
            for (int c = 0; c < 8; ++c) {
                ulonglong2 wv = *(const ulonglong2*)(wrA + 4 * c);
                ulonglong2 h0v = *(const ulonglong2*)(hbA + 4 * c);
                ulonglong2 h1v = *(const ulonglong2*)(hbA + 64  + 4 * c);
                ulonglong2 h2v = *(const ulonglong2*)(hbA + 128 + 4 * c);
                ulonglong2 h3v = *(const ulonglong2*)(hbA + 192 + 4 * c);
                a0 = ffma2(wv.x, h0v.x, a0);  e0 = ffma2(wv.y, h0v.y, e0);
                a1 = ffma2(wv.x, h1v.x, a1);  e1 = ffma2(wv.y, h1v.y, e1);
                a2 = ffma2(wv.x, h2v.x, a2);  e2 = ffma2(wv.y, h2v.y, e2);
                a3 = ffma2(wv.x, h3v.x, a3);  e3 = ffma2(wv.y, h3v.y, e3);
            }
            float* hg = sm + OFF_HG0 + kh * (Sh * G) + rA;
            hg[0]       = red2(a0, e0);
            hg[G]       = red2(a1, e1);
            hg[2 * G]   = red2(a2, e2);
            hg[3 * G]   = red2(a3, e3);
        }
        __syncthreads();

        // ---- Gate 0: update h0 (layer-0 output) --------------------------
        if (t < 256) gate0_upd(sm, gs, gj, l);
        __syncthreads();

        // ---- Phase B: ig1 = W_ih1 @ h0' , hg1 = W_hh1 @ h1 ---------------
        {
            u64 a0 = 0, a1 = 0, a2 = 0, a3 = 0, e0 = 0, e1 = 0, e2 = 0, e3 = 0;
            #pragma unroll
            for (int c = 0; c < 16; ++c) {
                ulonglong2 wv = *(const ulonglong2*)(wrB + 4 * c);
                ulonglong2 h0v = *(const ulonglong2*)(srcB + 4 * c);
                ulonglong2 h1v = *(const ulonglong2*)(srcB + 64  + 4 * c);
                ulonglong2 h2v = *(const ulonglong2*)(srcB + 128 + 4 * c);
                ulonglong2 h3v = *(const ulonglong2*)(srcB + 192 + 4 * c);
                a0 = ffma2(wv.x, h0v.x, a0);  e0 = ffma2(wv.y, h0v.y, e0);
                a1 = ffma2(wv.x, h1v.x, a1);  e1 = ffma2(wv.y, h1v.y, e1);
                a2 = ffma2(wv.x, h2v.x, a2);  e2 = ffma2(wv.y, h2v.y, e2);
                a3 = ffma2(wv.x, h3v.x, a3);  e3 = ffma2(wv.y, h3v.y, e3);
            }
            dstB[rB]         = red2(a0, e0);
            dstB[G + rB]     = red2(a1, e1);
            dstB[2 * G + rB] = red2(a2, e2);
            dstB[3 * G + rB] = red2(a3, e3);
        }
        __syncthreads();

        // ---- Gate 1: update h1, emit output ------------------------------
        if (t < 256) {
            float hn = gate1_upd(sm, gs, gj);
            outc[((long)gs * Lh + l) * Hh + gj] = hn;
        }
        // next phase A only reads h0 (guarded by the next two barriers)
    }
}

extern "C" void kernel_launch(void* const* d_in, const int* in_sizes, int n_in,
                              void* d_out, int out_size)
{
    const float* x     = (const float*)d_in[0];
    const float* w_ih0 = (const float*)d_in[1];
    const float* w_hh0 = (const float*)d_in[2];
    const float* b0    = (const float*)d_in[3];
    const float* bn0   = (const float*)d_in[4];
    const float* w_ih1 = (const float*)d_in[5];
    const float* w_hh1 = (const float*)d_in[6];
    const float* b1    = (const float*)d_in[7];
    const float* bn1   = (const float*)d_in[8];
    float* out = (float*)d_out;

    cudaFuncSetAttribute(gru2_kernel,
                         cudaFuncAttributeMaxDynamicSharedMemorySize, SMEM_BYTES);
    gru2_kernel<<<NCTA, NT, SMEM_BYTES>>>(x, w_ih0, w_hh0, b0, bn0,
                                          w_ih1, w_hh1, b1, bn1, out);
}

// round 2
// speedup vs baseline: 1.3000x; 1.3000x over previous
#include <cuda_runtime.h>

// ---------------------------------------------------------------------------
// Persistent fused 2-layer GRU.  B=16, C=32, L=2048, H=64.
// 512 sequences (scalar input), S=4 per CTA -> 128 CTAs, 256 threads.
// ALL weights cached in registers (144 floats/thread); smem only carries
// h-state, matvec partials, x slice, biases.  f32x2 packed FMAs.
// ---------------------------------------------------------------------------

namespace {
constexpr int Hh = 64;
constexpr int Lh = 2048;
constexpr int Ch = 32;
constexpr int Bh = 16;
constexpr int Sh = 4;
constexpr int NT = 256;                 // 8 warps, 2/SMSP
constexpr int NCTA = (Bh * Ch) / Sh;    // 128

// smem layout (float offsets)
constexpr int OFF_X    = 0;                      // x slice [2048][4]
constexpr int OFF_H0   = OFF_X   + Lh * Sh;      // 8192: h0 [4][64]
constexpr int OFF_H1   = OFF_H0  + Sh * Hh;      // 8448: h1 [4][64]
constexpr int OFF_P0   = OFF_H1  + Sh * Hh;      // 8704: hg0 partials [4][64][3][4]
constexpr int OFF_P1   = OFF_P0  + Sh * Hh * 12; // 11776: l1 partials [4][64][3][2][2]
constexpr int OFF_WIH0 = OFF_P1  + Sh * Hh * 12; // 14848
constexpr int OFF_B0   = OFF_WIH0 + 192;
constexpr int OFF_BN0  = OFF_B0   + 192;
constexpr int OFF_B1   = OFF_BN0  + Hh;
constexpr int OFF_BN1  = OFF_B1   + 192;
constexpr int SMEM_FLOATS = OFF_BN1 + Hh;
constexpr int SMEM_BYTES  = SMEM_FLOATS * 4;     // ~62.2 KB
}  // namespace

typedef unsigned long long u64;

__device__ __forceinline__ u64 ffma2(u64 a, u64 b, u64 c) {
    u64 d;
    asm("fma.rn.f32x2 %0, %1, %2, %3;" : "=l"(d) : "l"(a), "l"(b), "l"(c));
    return d;
}
__device__ __forceinline__ u64 pack2(float lo, float hi) {
    u64 r;
    asm("mov.b64 %0, {%1, %2};" : "=l"(r) : "f"(lo), "f"(hi));
    return r;
}
__device__ __forceinline__ float red1(u64 a) {
    float lo, hi;
    asm("mov.b64 {%0, %1}, %2;" : "=f"(lo), "=f"(hi) : "l"(a));
    return lo + hi;
}
__device__ __forceinline__ float sigf(float x)   { return 1.f / (1.f + __expf(-x)); }
__device__ __forceinline__ float tanhf_(float x) { return 1.f - 2.f / (__expf(2.f * x) + 1.f); }

__global__ __launch_bounds__(NT, 1)
void gru2_kernel(const float* __restrict__ x,
                 const float* __restrict__ w_ih0, const float* __restrict__ w_hh0,
                 const float* __restrict__ b0,    const float* __restrict__ bn0,
                 const float* __restrict__ w_ih1, const float* __restrict__ w_hh1,
                 const float* __restrict__ b1,    const float* __restrict__ bn1,
                 float* __restrict__ out)
{
    extern __shared__ float sm[];
    const int t = threadIdx.x;
    const int w = t >> 5;
    const int l32 = t & 31;
    const int m  = blockIdx.x;
    const int b  = m >> 3;
    const int c0 = (m & 7) * 4;

    // ---- one-time smem fills ------------------------------------------------
    for (int i = t; i < 192; i += NT) {
        sm[OFF_WIH0 + i] = w_ih0[i];
        sm[OFF_B0 + i]   = b0[i];
        sm[OFF_B1 + i]   = b1[i];
    }
    for (int i = t; i < Hh; i += NT) {
        sm[OFF_BN0 + i] = bn0[i];
        sm[OFF_BN1 + i] = bn1[i];
    }
    {
        const float* xg = x + (long)b * Lh * Ch + c0;
        for (int i = t; i < Lh; i += NT)
            *(float4*)(sm + OFF_X + i * 4) = *(const float4*)(xg + (long)i * Ch);
    }
    for (int i = t; i < 2 * Sh * Hh; i += NT) sm[OFF_H0 + i] = 0.f;

    // ---- weight slices -> registers ----------------------------------------
    // Phase A (hg0 = W_hh0 @ h0): 192 rows x 4 K-quarters = 768 tasks, 3/thread.
    const int Wa = w >> 2;          // row block (0/1)
    const int qa = w & 3;           // K quarter
    int rA0 = Wa * 96 + l32 * 3;    // rows rA0, rA0+1, rA0+2
    u64 wA[3][8];
    #pragma unroll
    for (int i = 0; i < 3; ++i)
        #pragma unroll
        for (int c = 0; c < 8; ++c) {
            const float* p = w_hh0 + (rA0 + i) * 64 + qa * 16 + c * 2;
            wA[i][c] = pack2(p[0], p[1]);
        }

    // Phase B (ig1 = W_ih1 @ h0', hg1 = W_hh1 @ h1): 384 rows x 2 halves, 3/thread.
    const int matB = (w >= 4) ? 1 : 0;
    const int wq = w & 3;
    const int hfB = wq >> 1;        // K half
    int rB0 = (wq & 1) * 96 + l32 * 3;
    const float* wsrc = matB ? w_hh1 : w_ih1;
    u64 wB[3][16];
    #pragma unroll
    for (int i = 0; i < 3; ++i)
        #pragma unroll
        for (int c = 0; c < 16; ++c) {
            const float* p = wsrc + (rB0 + i) * 64 + hfB * 32 + c * 2;
            wB[i][c] = pack2(p[0], p[1]);
        }
    __syncthreads();

    const int gs = t >> 6;          // gate phase: seq (warp-uniform)
    const int gj = t & 63;          // gate phase: hidden index
    float* outp = out + ((long)(b * Ch + c0 + gs) * Lh) * Hh + gj;

    const float* hqA = sm + OFF_H0 + qa * 16;
    const float* hqB = sm + (matB ? OFF_H1 : OFF_H0) + hfB * 32;

    for (int l = 0; l < Lh; ++l) {
        // ---- Phase A: hg0 quarter-partials ---------------------------------
        {
            u64 acc[3][4];
            #pragma unroll
            for (int i = 0; i < 3; ++i)
                #pragma unroll
                for (int s = 0; s < 4; ++s) acc[i][s] = 0;
            #pragma unroll
            for (int c = 0; c < 4; ++c) {
                u64 hv[4][2];
                #pragma unroll
                for (int s = 0; s < 4; ++s) {
                    ulonglong2 v = *(const ulonglong2*)(hqA + s * 64 + c * 4);
                    hv[s][0] = v.x; hv[s][1] = v.y;
                }
                #pragma unroll
                for (int i = 0; i < 3; ++i)
                    #pragma unroll
                    for (int s = 0; s < 4; ++s) {
                        acc[i][s] = ffma2(wA[i][2 * c],     hv[s][0], acc[i][s]);
                        acc[i][s] = ffma2(wA[i][2 * c + 1], hv[s][1], acc[i][s]);
                    }
            }
            #pragma unroll
            for (int i = 0; i < 3; ++i) {
                int r = rA0 + i, g = r >> 6, j = r & 63;
                #pragma unroll
                for (int s = 0; s < 4; ++s)
                    sm[OFF_P0 + ((s * 64 + j) * 3 + g) * 4 + qa] = red1(acc[i][s]);
            }
        }
        __syncthreads();

        // ---- Gate 0: h0' (all 256 threads, one (seq, j) each) --------------
        {
            float xv = sm[OFF_X + l * 4 + gs];
            const float* p = sm + OFF_P0 + (gs * 64 + gj) * 12;
            float4 P0 = *(const float4*)(p);
            float4 P1 = *(const float4*)(p + 4);
            float4 P2 = *(const float4*)(p + 8);
            float hr = (P0.x + P0.y) + (P0.z + P0.w);
            float hz = (P1.x + P1.y) + (P1.z + P1.w);
            float hn = (P2.x + P2.y) + (P2.z + P2.w);
            float ir  = fmaf(sm[OFF_WIH0 + gj],       xv, sm[OFF_B0 + gj]);
            float iz  = fmaf(sm[OFF_WIH0 + gj + 64],  xv, sm[OFF_B0 + gj + 64]);
            float in_ = fmaf(sm[OFF_WIH0 + gj + 128], xv, sm[OFF_B0 + gj + 128]);
            float r = sigf(ir + hr);
            float z = sigf(iz + hz);
            float n = tanhf_(in_ + r * (hn + sm[OFF_BN0 + gj]));
            float hp = sm[OFF_H0 + gs * 64 + gj];
            sm[OFF_H0 + gs * 64 + gj] = n + z * (hp - n);
        }
        __syncthreads();

        // ---- Phase B: ig1 / hg1 half-partials ------------------------------
        {
            u64 acc[3][4];
            #pragma unroll
            for (int i = 0; i < 3; ++i)
                #pragma unroll
                for (int s = 0; s < 4; ++s) acc[i][s] = 0;
            #pragma unroll
            for (int c = 0; c < 8; ++c) {
                u64 hv[4][2];
                #pragma unroll
                for (int s = 0; s < 4; ++s) {
                    ulonglong2 v = *(const ulonglong2*)(hqB + s * 64 + c * 4);
                    hv[s][0] = v.x; hv[s][1] = v.y;
                }
                #pragma unroll
                for (int i = 0; i < 3; ++i)
                    #pragma unroll
                    for (int s = 0; s < 4; ++s) {
                        acc[i][s] = ffma2(wB[i][2 * c],     hv[s][0], acc[i][s]);
                        acc[i][s] = ffma2(wB[i][2 * c + 1], hv[s][1], acc[i][s]);
                    }
            }
            #pragma unroll
            for (int i = 0; i < 3; ++i) {
                int r = rB0 + i, g = r >> 6, j = r & 63;
                #pragma unroll
                for (int s = 0; s < 4; ++s)
                    sm[OFF_P1 + ((s * 64 + j) * 3 + g) * 4 + matB * 2 + hfB] = red1(acc[i][s]);
            }
        }
        __syncthreads();

        // ---- Gate 1: h1', emit output --------------------------------------
        {
            const float* p = sm + OFF_P1 + (gs * 64 + gj) * 12;
            float4 P0 = *(const float4*)(p);       // r: {ig h0, ig h1, hg h0, hg h1}
            float4 P1 = *(const float4*)(p + 4);   // z
            float4 P2 = *(const float4*)(p + 8);   // n
            float pr  = (P0.x + P0.y) + (P0.z + P0.w) + sm[OFF_B1 + gj];
            float pz  = (P1.x + P1.y) + (P1.z + P1.w) + sm[OFF_B1 + gj + 64];
            float in_ = (P2.x + P2.y) + sm[OFF_B1 + gj + 128];
            float hgn = (P2.z + P2.w) + sm[OFF_BN1 + gj];
            float r = sigf(pr);
            float z = sigf(pz);
            float n = tanhf_(in_ + r * hgn);
            float hp = sm[OFF_H1 + gs * 64 + gj];
            float hnew = n + z * (hp - n);
            sm[OFF_H1 + gs * 64 + gj] = hnew;
            outp[(long)l * Hh] = hnew;
        }
        // next-step phase A reads h0 (guarded by the two barriers above)
    }
}

extern "C" void kernel_launch(void* const* d_in, const int* in_sizes, int n_in,
                              void* d_out, int out_size)
{
    const float* x     = (const float*)d_in[0];
    const float* w_ih0 = (const float*)d_in[1];
    const float* w_hh0 = (const float*)d_in[2];
    const float* b0    = (const float*)d_in[3];
    const float* bn0   = (const float*)d_in[4];
    const float* w_ih1 = (const float*)d_in[5];
    const float* w_hh1 = (const float*)d_in[6];
    const float* b1    = (const float*)d_in[7];
    const float* bn1   = (const float*)d_in[8];
    float* out = (float*)d_out;

    cudaFuncSetAttribute(gru2_kernel,
                         cudaFuncAttributeMaxDynamicSharedMemorySize, SMEM_BYTES);
    gru2_kernel<<<NCTA, NT, SMEM_BYTES>>>(x, w_ih0, w_hh0, b0, bn0,
                                          w_ih1, w_hh1, b1, bn1, out);
}